// round 3
// baseline (speedup 1.0000x reference)
#include <cuda_runtime.h>
#include <cuda_bf16.h>

// Problem constants
#define TT 512
#define BB 64
#define DD 1024
#define HH 1024
#define NBLK 128

typedef unsigned long long ull;

// SMEM layout for scan (floats)
#define SM_W        32768                  // wsm: [1024][32]
#define HST_U64_W   384                    // per warp: 2 bufs x 32 k x 6 u64
#define SM_RED      (SM_W + 8 * 2 * HST_U64_W)   // 32768 + 6144 = 38912
#define SM_TOT_F    (SM_RED + 2048)        // 40960 floats
#define SM_TOT_B    (SM_TOT_F * 4)         // 163840 bytes

// produce/consume flags: one per (t, rq, ct)
__device__ unsigned g_flag[TT * 4 * 32];

// ---------------------------------------------------------------------------
// f32x2 helpers (sm_100a packed fp32 — ptxas never emits these from C++)
// ---------------------------------------------------------------------------
__device__ __forceinline__ ull fma2(ull a, ull b, ull c) {
    ull d;
    asm("fma.rn.f32x2 %0, %1, %2, %3;" : "=l"(d) : "l"(a), "l"(b), "l"(c));
    return d;
}
__device__ __forceinline__ ull pack2(float x, float y) {
    ull d; asm("mov.b64 %0, {%1, %2};" : "=l"(d) : "f"(x), "f"(y)); return d;
}
__device__ __forceinline__ void unpack2(ull v, float& x, float& y) {
    asm("mov.b64 {%0, %1}, %2;" : "=f"(x), "=f"(y) : "l"(v));
}

__device__ __forceinline__ void wait_flag(const unsigned* p) {
    unsigned v;
    do {
        asm volatile("ld.acquire.gpu.global.b32 %0, [%1];" : "=r"(v) : "l"(p));
    } while (v == 0);
}

// ---------------------------------------------------------------------------
// Init: zero flags every launch (replay-deterministic)
// ---------------------------------------------------------------------------
__global__ void init_kernel() {
    int i = blockIdx.x * blockDim.x + threadIdx.x;
    if (i < TT * 4 * 32) g_flag[i] = 0u;
}

// ---------------------------------------------------------------------------
// Kernel 1: xproj = inputs @ W_xh + b  (f32x2 inner product, FFMA2 floor)
// BM=128, BN=64, BK=16, 256 threads, 8x4 microtile (rows paired)
// ---------------------------------------------------------------------------
__global__ __launch_bounds__(256) void xproj_kernel(
    const float* __restrict__ A,      // [32768, 1024]
    const float* __restrict__ W,      // [1024, 1024]
    const float* __restrict__ bias,   // [1024]
    float* __restrict__ out)          // [32768, 1024]
{
    __shared__ float As[16][128];     // As[k][m] (transposed)
    __shared__ float Bs[16][64];      // Bs[k][n]

    const int bm  = blockIdx.y * 128;
    const int bn  = blockIdx.x * 64;
    const int tid = threadIdx.x;
    const int tx  = tid & 15;         // col group (4 cols)
    const int ty  = tid >> 4;         // row group (8 rows)

    ull acc[4][4];                    // row pairs (2p,2p+1) x 4 cols
#pragma unroll
    for (int p = 0; p < 4; p++)
#pragma unroll
        for (int j = 0; j < 4; j++) acc[p][j] = 0ull;

    const int r_ld  = tid >> 1;
    const int kq_ld = (tid & 1) * 2;
    const int kk_ld = tid >> 4;
    const int cq_ld = tid & 15;

    for (int k0 = 0; k0 < DD; k0 += 16) {
#pragma unroll
        for (int i = 0; i < 2; i++) {
            float4 v = *(const float4*)&A[(size_t)(bm + r_ld) * DD + k0 + (kq_ld + i) * 4];
            As[(kq_ld + i) * 4 + 0][r_ld] = v.x;
            As[(kq_ld + i) * 4 + 1][r_ld] = v.y;
            As[(kq_ld + i) * 4 + 2][r_ld] = v.z;
            As[(kq_ld + i) * 4 + 3][r_ld] = v.w;
        }
        {
            float4 v = *(const float4*)&W[(size_t)(k0 + kk_ld) * HH + bn + cq_ld * 4];
            *(float4*)&Bs[kk_ld][cq_ld * 4] = v;
        }
        __syncthreads();

#pragma unroll
        for (int kk = 0; kk < 16; kk++) {
            ulonglong2 a0 = *(const ulonglong2*)&As[kk][ty * 8];       // rows (0,1),(2,3)
            ulonglong2 a1 = *(const ulonglong2*)&As[kk][ty * 8 + 4];   // rows (4,5),(6,7)
            float4 bq = *(const float4*)&Bs[kk][tx * 4];
            ull b0 = pack2(bq.x, bq.x);
            ull b1 = pack2(bq.y, bq.y);
            ull b2 = pack2(bq.z, bq.z);
            ull b3 = pack2(bq.w, bq.w);
            ull av[4] = {a0.x, a0.y, a1.x, a1.y};
#pragma unroll
            for (int p = 0; p < 4; p++) {
                acc[p][0] = fma2(av[p], b0, acc[p][0]);
                acc[p][1] = fma2(av[p], b1, acc[p][1]);
                acc[p][2] = fma2(av[p], b2, acc[p][2]);
                acc[p][3] = fma2(av[p], b3, acc[p][3]);
            }
        }
        __syncthreads();
    }

    float4 bv;
    bv.x = bias[bn + tx * 4 + 0];
    bv.y = bias[bn + tx * 4 + 1];
    bv.z = bias[bn + tx * 4 + 2];
    bv.w = bias[bn + tx * 4 + 3];
#pragma unroll
    for (int p = 0; p < 4; p++) {
        float lo0, hi0, lo1, hi1, lo2, hi2, lo3, hi3;
        unpack2(acc[p][0], lo0, hi0);
        unpack2(acc[p][1], lo1, hi1);
        unpack2(acc[p][2], lo2, hi2);
        unpack2(acc[p][3], lo3, hi3);
        int row0 = bm + ty * 8 + 2 * p;
        float4 o0; o0.x = lo0 + bv.x; o0.y = lo1 + bv.y; o0.z = lo2 + bv.z; o0.w = lo3 + bv.w;
        float4 o1; o1.x = hi0 + bv.x; o1.y = hi1 + bv.y; o1.z = hi2 + bv.z; o1.w = hi3 + bv.w;
        *(float4*)&out[(size_t)row0 * HH + bn + tx * 4] = o0;
        *(float4*)&out[(size_t)(row0 + 1) * HH + bn + tx * 4] = o1;
    }
}

// ---------------------------------------------------------------------------
// Kernel 2: persistent scan, flag-pipelined (NO global barrier).
//   Block (rq,ct): rows rq*16..+15, cols ct*32..+31, full K=1024.
//   Warp (s,rg): K slice s*256..+256, rows rg*8..+7 of the quad.
//   Consumers poll per-producer-tile flags chunk-by-chunk (32 k each),
//   round-robin from their own tile; staging double-buffered in SMEM.
//   h pairs (r, r+4) pre-packed as f32x2 in the staging buffer.
// ---------------------------------------------------------------------------
__global__ __launch_bounds__(256) void scan_kernel(
    const float* __restrict__ state,   // [64, 1024]
    const float* __restrict__ Whh,     // [1024, 1024]
    float* __restrict__ out,           // d_out
    int write_final)
{
    extern __shared__ float sm[];
    float* wsm    = sm;                        // [1024][32]
    ull*   hstAll = (ull*)(sm + SM_W);         // 8 warps x 384 u64
    float* red    = sm + SM_RED;               // [4][512]

    const int bid = blockIdx.x;
    const int tid = threadIdx.x;
    const int rq  = bid >> 5;
    const int ct  = bid & 31;

    const int lane = tid & 31;
    const int wid  = tid >> 5;
    const int s    = wid & 3;          // K slice
    const int rg   = wid >> 2;         // row group (8 rows)

    // W slice resident in SMEM for all 512 steps: wsm[k][c]
    for (int i = tid; i < 1024 * 32; i += 256)
        wsm[i] = Whh[(size_t)(i >> 5) * HH + ct * 32 + (i & 31)];

    const int R0 = rq * 16 + rg * 8;
    const int k4 = lane & 7;           // float4 index along k (coalesced LDG)
    const int rr = lane >> 3;          // 0..3 (row; also handles rr+4)
    ull* myhst = hstAll + wid * HST_U64_W;

    const int o0 = tid, o1 = tid + 256;
    const int gidx0 = (rq * 16 + (o0 >> 5)) * HH + ct * 32 + (o0 & 31);
    const int gidx1 = (rq * 16 + (o1 >> 5)) * HH + ct * 32 + (o1 & 31);
    const int cidx0 = ct & 7;          // start chunk offset (own tile first)

    __syncthreads();

    for (int t = 0; t < TT; t++) {
        const float* hsrc = (t == 0) ? state : (out + (size_t)(t - 1) * BB * HH);
        float* xp = out + (size_t)t * BB * HH;

        float xp0 = xp[gidx0];
        float xp1 = xp[gidx1];

        ull acc0 = 0, acc1 = 0, acc2 = 0, acc3 = 0;

        // prologue: wait + load chunk 0
        int c = 8 * s + cidx0;
        if (t > 0) {
            if (lane == 0) wait_flag(&g_flag[((t - 1) * 4 + rq) * 32 + c]);
            __syncwarp();
        }
        const float* src = &hsrc[(size_t)(R0 + rr) * HH + c * 32 + k4 * 4];
        float4 v0 = __ldcg((const float4*)src);
        float4 v1 = __ldcg((const float4*)(src + 4 * HH));
        int kw = c * 32;
        int b = 0;

#pragma unroll 1
        for (int ci = 0; ci < 8; ci++) {
            float4 u0, u1;
            int kwn = 0;
            if (ci < 7) {
                int c2 = 8 * s + ((cidx0 + ci + 1) & 7);
                if (t > 0) {
                    if (lane == 0) wait_flag(&g_flag[((t - 1) * 4 + rq) * 32 + c2]);
                    __syncwarp();
                }
                const float* src2 = &hsrc[(size_t)(R0 + rr) * HH + c2 * 32 + k4 * 4];
                u0 = __ldcg((const float4*)src2);
                u1 = __ldcg((const float4*)(src2 + 4 * HH));
                kwn = c2 * 32;
            }
            // stage current chunk: pack rows (rr, rr+4) as f32x2, STS.64
            {
                ull* d = myhst + b * 192 + (k4 * 4) * 6 + rr;
                d[0]  = pack2(v0.x, v1.x);
                d[6]  = pack2(v0.y, v1.y);
                d[12] = pack2(v0.z, v1.z);
                d[18] = pack2(v0.w, v1.w);
            }
            __syncwarp();
            // compute chunk (32 k): 4 FFMA2 per k, LDG for next chunk in flight
            {
                const float* wb = &wsm[kw * 32 + lane];
                const ulonglong2* hb = (const ulonglong2*)(myhst + b * 192);
#pragma unroll
                for (int k = 0; k < 32; k++) {
                    float w = wb[k * 32];
                    ull w2 = pack2(w, w);
                    ulonglong2 hA = hb[k * 3];       // pairs (r0,r4),(r1,r5)
                    ulonglong2 hB = hb[k * 3 + 1];   // pairs (r2,r6),(r3,r7)
                    acc0 = fma2(hA.x, w2, acc0);
                    acc1 = fma2(hA.y, w2, acc1);
                    acc2 = fma2(hB.x, w2, acc2);
                    acc3 = fma2(hB.y, w2, acc3);
                }
            }
            v0 = u0; v1 = u1; kw = kwn; b ^= 1;
            __syncwarp();
        }

        // intra-block split-K reduce through SMEM
        {
            float lo, hi;
            unpack2(acc0, lo, hi);
            red[s * 512 + (rg * 8 + 0) * 32 + lane] = lo;
            red[s * 512 + (rg * 8 + 4) * 32 + lane] = hi;
            unpack2(acc1, lo, hi);
            red[s * 512 + (rg * 8 + 1) * 32 + lane] = lo;
            red[s * 512 + (rg * 8 + 5) * 32 + lane] = hi;
            unpack2(acc2, lo, hi);
            red[s * 512 + (rg * 8 + 2) * 32 + lane] = lo;
            red[s * 512 + (rg * 8 + 6) * 32 + lane] = hi;
            unpack2(acc3, lo, hi);
            red[s * 512 + (rg * 8 + 3) * 32 + lane] = lo;
            red[s * 512 + (rg * 8 + 7) * 32 + lane] = hi;
        }
        __syncthreads();

        // phase 2: sum 4 slices + xp, tanh, write h_t in place over xp_t
        {
            float vv0 = red[o0] + red[512 + o0] + red[1024 + o0] + red[1536 + o0] + xp0;
            float vv1 = red[o1] + red[512 + o1] + red[1024 + o1] + red[1536 + o1] + xp1;
            float h0 = tanhf(vv0);
            float h1 = tanhf(vv1);
            xp[gidx0] = h0;
            xp[gidx1] = h1;
            if (write_final && t == TT - 1) {
                out[(size_t)TT * BB * HH + gidx0] = h0;
                out[(size_t)TT * BB * HH + gidx1] = h1;
            }
        }
        __syncthreads();   // all h STGs of this block ordered before flag release

        if (tid == 0 && t < TT - 1)
            asm volatile("st.release.gpu.global.b32 [%0], %1;"
                         :: "l"(&g_flag[(t * 4 + rq) * 32 + ct]), "r"(1u));
    }
}

// ---------------------------------------------------------------------------
extern "C" void kernel_launch(void* const* d_in, const int* in_sizes, int n_in,
                              void* d_out, int out_size) {
    const float* inputs = (const float*)d_in[0];   // [T,B,D]
    const float* state  = (const float*)d_in[1];   // [B,H]
    const float* W_xh   = (const float*)d_in[2];   // [D,H]
    const float* W_hh   = (const float*)d_in[3];   // [H,H]
    const float* b_h    = (const float*)d_in[4];   // [H]
    float* out = (float*)d_out;

    int write_final = (out_size >= TT * BB * HH + BB * HH) ? 1 : 0;

    static int smem_set = 0;
    if (!smem_set) {
        cudaFuncSetAttribute(scan_kernel,
                             cudaFuncAttributeMaxDynamicSharedMemorySize,
                             SM_TOT_B);
        smem_set = 1;
    }

    init_kernel<<<256, 256>>>();

    dim3 g1(HH / 64, (TT * BB) / 128);
    xproj_kernel<<<g1, 256>>>(inputs, W_xh, b_h, out);

    scan_kernel<<<NBLK, 256, SM_TOT_B>>>(state, W_hh, out, write_final);
}

// round 4
// speedup vs baseline: 2.5589x; 2.5589x over previous
#include <cuda_runtime.h>
#include <cuda_bf16.h>

// Problem constants
#define TT 512
#define BB 64
#define DD 1024
#define HH 1024
#define NBLK 128

typedef unsigned long long ull;

// SMEM layout for scan (floats)
#define SM_W        32768                        // wsm: [1024][32]
#define HST_U64_W   384                          // per warp: 2 bufs x 32 k x 6 u64
#define SM_RED      (SM_W + 8 * 2 * HST_U64_W)   // 32768 + 6144 = 38912
#define SM_TOT_F    (SM_RED + 2048)              // 40960 floats
#define SM_TOT_B    (SM_TOT_F * 4)               // 163840 bytes

__device__ unsigned g_bar[TT];                   // one counter per step

// ---------------------------------------------------------------------------
// f32x2 helpers (packed fp32 FFMA2 — ptxas never emits from C++)
// ---------------------------------------------------------------------------
__device__ __forceinline__ ull fma2(ull a, ull b, ull c) {
    ull d;
    asm("fma.rn.f32x2 %0, %1, %2, %3;" : "=l"(d) : "l"(a), "l"(b), "l"(c));
    return d;
}
__device__ __forceinline__ ull pack2(float x, float y) {
    ull d; asm("mov.b64 %0, {%1, %2};" : "=l"(d) : "f"(x), "f"(y)); return d;
}
__device__ __forceinline__ void unpack2(ull v, float& x, float& y) {
    asm("mov.b64 {%0, %1}, %2;" : "=f"(x), "=f"(y) : "l"(v));
}

// ---------------------------------------------------------------------------
__global__ void init_kernel() {
    int i = blockIdx.x * blockDim.x + threadIdx.x;
    if (i < TT) g_bar[i] = 0u;
}

// ---------------------------------------------------------------------------
// Kernel 1: xproj = inputs @ W_xh + b  (FFMA2 inner product)
// BM=128, BN=64, BK=16, 256 threads, 8x4 microtile with rows paired
// ---------------------------------------------------------------------------
__global__ __launch_bounds__(256) void xproj_kernel(
    const float* __restrict__ A,      // [32768, 1024]
    const float* __restrict__ W,      // [1024, 1024]
    const float* __restrict__ bias,   // [1024]
    float* __restrict__ out)          // [32768, 1024]
{
    __shared__ float As[16][128];     // As[k][m] (transposed)
    __shared__ float Bs[16][64];      // Bs[k][n]

    const int bm  = blockIdx.y * 128;
    const int bn  = blockIdx.x * 64;
    const int tid = threadIdx.x;
    const int tx  = tid & 15;
    const int ty  = tid >> 4;

    ull acc[4][4];
#pragma unroll
    for (int p = 0; p < 4; p++)
#pragma unroll
        for (int j = 0; j < 4; j++) acc[p][j] = 0ull;

    const int r_ld  = tid >> 1;
    const int kq_ld = (tid & 1) * 2;
    const int kk_ld = tid >> 4;
    const int cq_ld = tid & 15;

    for (int k0 = 0; k0 < DD; k0 += 16) {
#pragma unroll
        for (int i = 0; i < 2; i++) {
            float4 v = *(const float4*)&A[(size_t)(bm + r_ld) * DD + k0 + (kq_ld + i) * 4];
            As[(kq_ld + i) * 4 + 0][r_ld] = v.x;
            As[(kq_ld + i) * 4 + 1][r_ld] = v.y;
            As[(kq_ld + i) * 4 + 2][r_ld] = v.z;
            As[(kq_ld + i) * 4 + 3][r_ld] = v.w;
        }
        {
            float4 v = *(const float4*)&W[(size_t)(k0 + kk_ld) * HH + bn + cq_ld * 4];
            *(float4*)&Bs[kk_ld][cq_ld * 4] = v;
        }
        __syncthreads();

#pragma unroll
        for (int kk = 0; kk < 16; kk++) {
            ulonglong2 a0 = *(const ulonglong2*)&As[kk][ty * 8];
            ulonglong2 a1 = *(const ulonglong2*)&As[kk][ty * 8 + 4];
            float4 bq = *(const float4*)&Bs[kk][tx * 4];
            ull b0 = pack2(bq.x, bq.x);
            ull b1 = pack2(bq.y, bq.y);
            ull b2 = pack2(bq.z, bq.z);
            ull b3 = pack2(bq.w, bq.w);
            ull av[4] = {a0.x, a0.y, a1.x, a1.y};
#pragma unroll
            for (int p = 0; p < 4; p++) {
                acc[p][0] = fma2(av[p], b0, acc[p][0]);
                acc[p][1] = fma2(av[p], b1, acc[p][1]);
                acc[p][2] = fma2(av[p], b2, acc[p][2]);
                acc[p][3] = fma2(av[p], b3, acc[p][3]);
            }
        }
        __syncthreads();
    }

    float4 bv;
    bv.x = bias[bn + tx * 4 + 0];
    bv.y = bias[bn + tx * 4 + 1];
    bv.z = bias[bn + tx * 4 + 2];
    bv.w = bias[bn + tx * 4 + 3];
#pragma unroll
    for (int p = 0; p < 4; p++) {
        float lo0, hi0, lo1, hi1, lo2, hi2, lo3, hi3;
        unpack2(acc[p][0], lo0, hi0);
        unpack2(acc[p][1], lo1, hi1);
        unpack2(acc[p][2], lo2, hi2);
        unpack2(acc[p][3], lo3, hi3);
        int row0 = bm + ty * 8 + 2 * p;
        float4 o0; o0.x = lo0 + bv.x; o0.y = lo1 + bv.y; o0.z = lo2 + bv.z; o0.w = lo3 + bv.w;
        float4 o1; o1.x = hi0 + bv.x; o1.y = hi1 + bv.y; o1.z = hi2 + bv.z; o1.w = hi3 + bv.w;
        *(float4*)&out[(size_t)row0 * HH + bn + tx * 4] = o0;
        *(float4*)&out[(size_t)(row0 + 1) * HH + bn + tx * 4] = o1;
    }
}

// ---------------------------------------------------------------------------
// Global barrier: one per step (R2-proven structure)
// ---------------------------------------------------------------------------
__device__ __forceinline__ void gbar(int slot) {
    __syncthreads();
    if (threadIdx.x == 0) {
        __threadfence();
        atomicAdd(&g_bar[slot], 1u);
        volatile unsigned* p = &g_bar[slot];
        while (*p < (unsigned)NBLK) { }
    }
    __syncthreads();
    __threadfence();
}

// ---------------------------------------------------------------------------
// Kernel 2: persistent scan. Global barrier per step; per-warp staging
// (warp-local double buffer, __syncwarp only); FFMA2 inner loop with
// h row pairs (r, r+4) pre-packed at stage time.
// Block (rq,ct): rows rq*16..+15, cols ct*32..+31, full K=1024.
// Warp (s,rg): K slice s*256..+256, rows rg*8..+7.
// ---------------------------------------------------------------------------
__global__ __launch_bounds__(256) void scan_kernel(
    const float* __restrict__ state,   // [64, 1024]
    const float* __restrict__ Whh,     // [1024, 1024]
    float* __restrict__ out,           // d_out
    int write_final)
{
    extern __shared__ float sm[];
    float* wsm    = sm;                        // [1024][32]
    ull*   hstAll = (ull*)(sm + SM_W);         // 8 warps x 384 u64
    float* red    = sm + SM_RED;               // [4][512]

    const int bid = blockIdx.x;
    const int tid = threadIdx.x;
    const int rq  = bid >> 5;
    const int ct  = bid & 31;

    const int lane = tid & 31;
    const int wid  = tid >> 5;
    const int s    = wid & 3;          // K slice
    const int rg   = wid >> 2;         // row group

    for (int i = tid; i < 1024 * 32; i += 256)
        wsm[i] = Whh[(size_t)(i >> 5) * HH + ct * 32 + (i & 31)];

    const int R0 = rq * 16 + rg * 8;
    const int k4 = lane & 7;           // float4 index along k
    const int rr = lane >> 3;          // 0..3 (also covers rr+4)
    ull* myhst = hstAll + wid * HST_U64_W;

    const int o0 = tid, o1 = tid + 256;
    const int gidx0 = (rq * 16 + (o0 >> 5)) * HH + ct * 32 + (o0 & 31);
    const int gidx1 = (rq * 16 + (o1 >> 5)) * HH + ct * 32 + (o1 & 31);

    __syncthreads();

    for (int t = 0; t < TT; t++) {
        const float* hsrc = (t == 0) ? state : (out + (size_t)(t - 1) * BB * HH);
        float* xp = out + (size_t)t * BB * HH;

        float xp0 = xp[gidx0];
        float xp1 = xp[gidx1];

        ull acc0 = 0, acc1 = 0, acc2 = 0, acc3 = 0;

        // prologue: load chunk 0 of this warp's K slice
        const float* src = &hsrc[(size_t)(R0 + rr) * HH + s * 256 + k4 * 4];
        float4 v0 = __ldcg((const float4*)src);
        float4 v1 = __ldcg((const float4*)(src + 4 * HH));
        int b = 0;

#pragma unroll 1
        for (int ci = 0; ci < 8; ci++) {
            float4 u0, u1;
            if (ci < 7) {   // prefetch next chunk (in flight during compute)
                const float* s2 = src + (ci + 1) * 32;
                u0 = __ldcg((const float4*)s2);
                u1 = __ldcg((const float4*)(s2 + 4 * HH));
            }
            // stage current chunk: pack rows (rr, rr+4) as f32x2
            {
                ull* d = myhst + b * 192 + (k4 * 4) * 6 + rr;
                d[0]  = pack2(v0.x, v1.x);
                d[6]  = pack2(v0.y, v1.y);
                d[12] = pack2(v0.z, v1.z);
                d[18] = pack2(v0.w, v1.w);
            }
            __syncwarp();
            // compute chunk: 4 FFMA2 per k
            {
                const float* wb = &wsm[(s * 256 + ci * 32) * 32 + lane];
                const ulonglong2* hb = (const ulonglong2*)(myhst + b * 192);
#pragma unroll
                for (int k = 0; k < 32; k++) {
                    float w = wb[k * 32];                // conflict-free LDS.32
                    ull w2 = pack2(w, w);
                    ulonglong2 hA = hb[k * 3];           // broadcast LDS.128
                    ulonglong2 hB = hb[k * 3 + 1];
                    acc0 = fma2(hA.x, w2, acc0);
                    acc1 = fma2(hA.y, w2, acc1);
                    acc2 = fma2(hB.x, w2, acc2);
                    acc3 = fma2(hB.y, w2, acc3);
                }
            }
            v0 = u0; v1 = u1; b ^= 1;
            __syncwarp();
        }

        // intra-block split-K reduce through SMEM
        {
            float lo, hi;
            unpack2(acc0, lo, hi);
            red[s * 512 + (rg * 8 + 0) * 32 + lane] = lo;
            red[s * 512 + (rg * 8 + 4) * 32 + lane] = hi;
            unpack2(acc1, lo, hi);
            red[s * 512 + (rg * 8 + 1) * 32 + lane] = lo;
            red[s * 512 + (rg * 8 + 5) * 32 + lane] = hi;
            unpack2(acc2, lo, hi);
            red[s * 512 + (rg * 8 + 2) * 32 + lane] = lo;
            red[s * 512 + (rg * 8 + 6) * 32 + lane] = hi;
            unpack2(acc3, lo, hi);
            red[s * 512 + (rg * 8 + 3) * 32 + lane] = lo;
            red[s * 512 + (rg * 8 + 7) * 32 + lane] = hi;
        }
        __syncthreads();

        // phase 2: sum 4 slices + xp, tanh, write h_t in place over xp_t
        {
            float vv0 = red[o0] + red[512 + o0] + red[1024 + o0] + red[1536 + o0] + xp0;
            float vv1 = red[o1] + red[512 + o1] + red[1024 + o1] + red[1536 + o1] + xp1;
            float h0 = tanhf(vv0);
            float h1 = tanhf(vv1);
            xp[gidx0] = h0;
            xp[gidx1] = h1;
            if (write_final && t == TT - 1) {
                out[(size_t)TT * BB * HH + gidx0] = h0;
                out[(size_t)TT * BB * HH + gidx1] = h1;
            }
        }

        gbar(t);
    }
}

// ---------------------------------------------------------------------------
extern "C" void kernel_launch(void* const* d_in, const int* in_sizes, int n_in,
                              void* d_out, int out_size) {
    const float* inputs = (const float*)d_in[0];   // [T,B,D]
    const float* state  = (const float*)d_in[1];   // [B,H]
    const float* W_xh   = (const float*)d_in[2];   // [D,H]
    const float* W_hh   = (const float*)d_in[3];   // [H,H]
    const float* b_h    = (const float*)d_in[4];   // [H]
    float* out = (float*)d_out;

    int write_final = (out_size >= TT * BB * HH + BB * HH) ? 1 : 0;

    static int smem_set = 0;
    if (!smem_set) {
        cudaFuncSetAttribute(scan_kernel,
                             cudaFuncAttributeMaxDynamicSharedMemorySize,
                             SM_TOT_B);
        smem_set = 1;
    }

    init_kernel<<<2, 256>>>();

    dim3 g1(HH / 64, (TT * BB) / 128);
    xproj_kernel<<<g1, 256>>>(inputs, W_xh, b_h, out);

    scan_kernel<<<NBLK, 256, SM_TOT_B>>>(state, W_hh, out, write_final);
}